// round 6
// baseline (speedup 1.0000x reference)
#include <cuda_runtime.h>
#include <math.h>

// Problem constants (fixed by the dataset's setup_inputs)
#define BN   1000      // rois per image
#define NPAD 1024      // padded to power of two for bitonic sort
#define CC   81        // classes
#define KK   100       // max detections
#define FF   1024      // feature dim
#define META_STRIDE (12 + CC)

#define MIN_CONF 0.7f
#define NMS_THR  0.3f
#define KEY_INVALID 3.0e38f

#define NTHR 1024      // threads per detect CTA

// order-preserving float -> uint32 (ascending)
__device__ __forceinline__ unsigned int float_orderable(float f) {
    unsigned int u = __float_as_uint(f);
    return u ^ ((u >> 31) ? 0xFFFFFFFFu : 0x80000000u);
}

// =====================================================================
// Kernel A: per-image refine + stable sort + class-aware NMS.
// One CTA (1024 threads) per image. Phase 1 uses one warp per roi with
// coalesced class loads + shuffle argmax. Kept roi index is smuggled
// (as float bits) into element 0 of each feature row (read by Kernel B).
// =====================================================================
__global__ __launch_bounds__(NTHR)
void detect_kernel(const float* __restrict__ rois,
                   const float* __restrict__ probs,
                   const float* __restrict__ deltas,
                   const float* __restrict__ meta,
                   float* __restrict__ det_out,
                   float* __restrict__ feat_out)
{
    const int b    = blockIdx.x;
    const int tid  = threadIdx.x;
    const int wid  = tid >> 5;
    const int lane = tid & 31;

    __shared__ unsigned long long s_kv[NPAD];     // (orderable key << 32) | idx
    __shared__ float s_y1[NPAD], s_x1[NPAD], s_y2[NPAD], s_x2[NPAD];
    __shared__ float s_score[NPAD];
    __shared__ int   s_cls[NPAD];
    __shared__ int   s_counts[CC];
    __shared__ int   s_karr[KK], s_kcls[KK];
    __shared__ float s_ky1[KK], s_kx1[KK], s_ky2[KK], s_kx2[KK], s_karea[KK];
    __shared__ int   s_nk;

    // window from image_meta (shape from row 0, window per row)
    const float sy = meta[4] - 1.0f;
    const float sx = meta[5] - 1.0f;
    const float wy1 =  meta[(size_t)b * META_STRIDE + 7]          / sy;
    const float wx1 =  meta[(size_t)b * META_STRIDE + 8]          / sx;
    const float wy2 = (meta[(size_t)b * META_STRIDE + 9] - 1.0f)  / sy;
    const float wx2 = (meta[(size_t)b * META_STRIDE + 10] - 1.0f) / sx;

    for (int c = tid; c < CC; c += NTHR) s_counts[c] = 0;

    const unsigned long long KV_INVALID =
        ((unsigned long long)float_orderable(KEY_INVALID) << 32);

    // ---- Phase 1: warp-per-roi argmax (coalesced), decode, clip ----
    // 32 warps; warp w handles rois w, w+32, ... ; pad slots done by stride loop below.
    for (int i = wid; i < BN; i += 32) {
        const size_t gi = (size_t)b * BN + i;
        const float* pr = probs + gi * CC;

        // lanes cover classes lane, lane+32, lane+64 (coalesced)
        float v0 = pr[lane];
        float v1 = pr[lane + 32];                       // lane+32 <= 63 < 81 always
        float v2 = (lane + 64 < CC) ? pr[lane + 64] : -1.0f;

        float bv; int bc;
        // per-lane best of its (up to) 3 classes, prefer smallest class on tie
        bv = v0; bc = lane;
        if (v1 > bv) { bv = v1; bc = lane + 32; }
        if (v2 > bv) { bv = v2; bc = lane + 64; }
        // warp reduce: max value, min index among equals (== first-max)
        #pragma unroll
        for (int off = 16; off > 0; off >>= 1) {
            const float ov = __shfl_xor_sync(0xffffffffu, bv, off);
            const int   oc = __shfl_xor_sync(0xffffffffu, bc, off);
            if (ov > bv || (ov == bv && oc < bc)) { bv = ov; bc = oc; }
        }

        if (lane == 0) {
            const float* dl = deltas + (gi * CC + bc) * 4;
            const float dy = dl[0] * 0.1f;
            const float dx = dl[1] * 0.1f;
            const float dh = dl[2] * 0.2f;
            const float dw = dl[3] * 0.2f;

            const float* rr = rois + gi * 4;
            float y1 = rr[0], x1 = rr[1], y2 = rr[2], x2 = rr[3];
            const float h0 = y2 - y1, w0 = x2 - x1;
            const float cy = y1 + 0.5f * h0 + dy * h0;
            const float cx = x1 + 0.5f * w0 + dx * w0;
            const float hh = h0 * expf(dh);
            const float ww = w0 * expf(dw);
            y1 = cy - 0.5f * hh;
            x1 = cx - 0.5f * ww;
            y2 = y1 + hh;
            x2 = x1 + ww;
            // clip to window
            y1 = fminf(fmaxf(y1, wy1), wy2);
            x1 = fminf(fmaxf(x1, wx1), wx2);
            y2 = fminf(fmaxf(y2, wy1), wy2);
            x2 = fminf(fmaxf(x2, wx1), wx2);

            const bool valid = (bc > 0) && (bv >= MIN_CONF);
            const float key  = valid ? -bv : KEY_INVALID;

            s_y1[i] = y1; s_x1[i] = x1; s_y2[i] = y2; s_x2[i] = x2;
            s_score[i] = bv;
            s_cls[i]   = bc;
            s_kv[i] = ((unsigned long long)float_orderable(key) << 32)
                      | (unsigned int)i;
        }
    }
    // pad slots
    for (int i = BN + tid; i < NPAD; i += NTHR)
        s_kv[i] = KV_INVALID | (unsigned int)i;
    __syncthreads();

    // ---- Phase 2: bitonic sort of packed (key,idx) -> stable argsort ----
    // 1024 threads, one element-pair owner per compare-exchange.
    for (int k = 2; k <= NPAD; k <<= 1) {
        for (int j = k >> 1; j > 0; j >>= 1) {
            const int i   = tid;
            const int ixj = i ^ j;
            if (ixj > i) {
                const bool up = ((i & k) == 0);
                const unsigned long long a = s_kv[i];
                const unsigned long long c = s_kv[ixj];
                if ((a > c) == up) {
                    s_kv[i]   = c;
                    s_kv[ixj] = a;
                }
            }
            __syncthreads();
        }
    }

    // ---- Phase 3: greedy class-aware NMS (warp 0 only) ----
    if (tid < 32) {
        int nk = 0;
        for (int pos = 0; pos < BN; pos++) {
            const unsigned long long kv = s_kv[pos];
            if (kv >= KV_INVALID) break;                  // no more valid candidates
            const int j = (int)(kv & 0xFFFFFFFFu);
            const int c = s_cls[j];
            if (s_counts[c] >= KK) continue;              // class quota full

            const float cy1 = s_y1[j], cx1 = s_x1[j];
            const float cy2 = s_y2[j], cx2 = s_x2[j];
            const float ca  = (cy2 - cy1) * (cx2 - cx1);

            bool sup = false;
            for (int m = lane; m < nk; m += 32) {
                if (s_kcls[m] == c) {
                    const float yy1 = fmaxf(cy1, s_ky1[m]);
                    const float xx1 = fmaxf(cx1, s_kx1[m]);
                    const float yy2 = fminf(cy2, s_ky2[m]);
                    const float xx2 = fminf(cx2, s_kx2[m]);
                    const float inter = fmaxf(yy2 - yy1, 0.0f) * fmaxf(xx2 - xx1, 0.0f);
                    const float uni   = ca + s_karea[m] - inter;
                    if (inter / fmaxf(uni, 1e-8f) > NMS_THR) sup = true;
                }
            }
            if (__any_sync(0xffffffffu, sup)) continue;

            if (lane == 0) {
                s_karr[nk]  = j;
                s_kcls[nk]  = c;
                s_ky1[nk]   = cy1; s_kx1[nk] = cx1;
                s_ky2[nk]   = cy2; s_kx2[nk] = cx2;
                s_karea[nk] = ca;
                s_counts[c] += 1;
            }
            __syncwarp();
            nk++;
            if (nk == KK) break;                          // only first K kept matter
        }
        if (lane == 0) s_nk = nk;
    }
    __syncthreads();

    // ---- Phase 4: det rows + smuggle kept index into feat row slot 0 ----
    const int nk = s_nk;
    for (int k = tid; k < KK; k += NTHR) {
        const size_t bk = (size_t)b * KK + k;
        float* o = det_out + bk * 6;
        int j = -1;
        if (k < nk) {
            j = s_karr[k];
            o[0] = s_ky1[k];
            o[1] = s_kx1[k];
            o[2] = s_ky2[k];
            o[3] = s_kx2[k];
            o[4] = (float)s_kcls[k];
            o[5] = s_score[j];
        } else {
            o[0] = 0.0f; o[1] = 0.0f; o[2] = 0.0f;
            o[3] = 0.0f; o[4] = 0.0f; o[5] = 0.0f;
        }
        feat_out[bk * FF] = __int_as_float(j);   // overwritten by Kernel B
    }
}

// =====================================================================
// Kernel B: feature gather. Reads the roi index from dst[0] (written by
// Kernel A), broadcasts it, then copies/zero-fills the full row.
// =====================================================================
__global__ __launch_bounds__(256)
void feat_gather_kernel(const float* __restrict__ obj_feat,
                        float* __restrict__ feat_out)
{
    const int bk = blockIdx.x;            // b*KK + k
    const int b  = bk / KK;
    const int t  = threadIdx.x;           // 256 threads x float4 = 1024 floats

    __shared__ int sj;
    float* dst = feat_out + (size_t)bk * FF;
    if (t == 0) sj = __float_as_int(dst[0]);
    __syncthreads();
    const int j = sj;

    float4* d4 = (float4*)dst;
    if (j >= 0) {
        const float4* s4 = (const float4*)(obj_feat + ((size_t)b * BN + j) * FF);
        d4[t] = s4[t];
    } else {
        d4[t] = make_float4(0.0f, 0.0f, 0.0f, 0.0f);
    }
}

extern "C" void kernel_launch(void* const* d_in, const int* in_sizes, int n_in,
                              void* d_out, int out_size)
{
    const float* rois     = (const float*)d_in[0];
    const float* fpnclass = (const float*)d_in[1];
    const float* fpnbbox  = (const float*)d_in[2];
    const float* objfeat  = (const float*)d_in[3];
    const float* meta     = (const float*)d_in[4];

    const int B = in_sizes[0] / (BN * 4);

    float* det_out  = (float*)d_out;                         // (B, K, 6)
    float* feat_out = (float*)d_out + (size_t)B * KK * 6;    // (B, K, 1, 1, F)

    detect_kernel<<<B, NTHR>>>(rois, fpnclass, fpnbbox, meta, det_out, feat_out);
    feat_gather_kernel<<<B * KK, 256>>>(objfeat, feat_out);
}

// round 7
// speedup vs baseline: 1.7412x; 1.7412x over previous
#include <cuda_runtime.h>
#include <math.h>

// Problem constants (fixed by the dataset's setup_inputs)
#define BN   1000      // rois per image
#define NPAD 1024      // max candidates (compacted)
#define CC   81        // classes
#define KK   100       // max detections
#define FF   1024      // feature dim
#define META_STRIDE (12 + CC)

#define MIN_CONF 0.7f
#define NMS_THR  0.3f

#define NTHR 1024      // threads per detect CTA

// order-preserving float -> uint32 (ascending)
__device__ __forceinline__ unsigned int float_orderable(float f) {
    unsigned int u = __float_as_uint(f);
    return u ^ ((u >> 31) ? 0xFFFFFFFFu : 0x80000000u);
}

// =====================================================================
// Kernel A: per-image refine + compaction + per-class parallel NMS.
// One CTA (1024 threads) per image. No global sort: all ordering is
// resolved by counting comparisons of packed (key,idx) u64s, which is
// exactly the stable argsort order of the reference. The greedy NMS
// scan decomposes per class (suppression and quotas are class-local),
// so each class's chain runs on its own warp.
// Kept roi index is smuggled (as float bits) into element 0 of each
// feature row (read back by Kernel B).
// =====================================================================
__global__ __launch_bounds__(NTHR)
void detect_kernel(const float* __restrict__ rois,
                   const float* __restrict__ probs,
                   const float* __restrict__ deltas,
                   const float* __restrict__ meta,
                   float* __restrict__ det_out,
                   float* __restrict__ feat_out)
{
    const int b    = blockIdx.x;
    const int tid  = threadIdx.x;
    const int wid  = tid >> 5;
    const int lane = tid & 31;

    // candidate arrays (compacted valid candidates, slot order arbitrary;
    // all ordering is derived from c_kv, so results are deterministic)
    __shared__ unsigned long long c_kv[NPAD];    // (orderable(-score) << 32) | roi_idx
    __shared__ float c_y1[NPAD], c_x1[NPAD], c_y2[NPAD], c_x2[NPAD];
    __shared__ float c_score[NPAD];
    __shared__ int   c_cls[NPAD];
    __shared__ int   c_wr[NPAD];                 // within-class rank
    __shared__ int   s_clist[NPAD];              // per-class candidate slots, in-class order
    __shared__ unsigned char s_kept[NPAD];
    __shared__ int   s_ccount[CC];               // candidates per class
    __shared__ int   s_cstart[CC];               // exclusive prefix of s_ccount
    __shared__ int   s_nv;

    // window from image_meta (shape from row 0, window per row)
    const float sy = meta[4] - 1.0f;
    const float sx = meta[5] - 1.0f;
    const float wy1 =  meta[(size_t)b * META_STRIDE + 7]          / sy;
    const float wx1 =  meta[(size_t)b * META_STRIDE + 8]          / sx;
    const float wy2 = (meta[(size_t)b * META_STRIDE + 9] - 1.0f)  / sy;
    const float wx2 = (meta[(size_t)b * META_STRIDE + 10] - 1.0f) / sx;

    // ---- Phase 0: init ----
    if (tid == 0) s_nv = 0;
    for (int c = tid; c < CC; c += NTHR) s_ccount[c] = 0;
    for (int i = tid; i < NPAD; i += NTHR) s_kept[i] = 0;
    __syncthreads();

    // ---- Phase 1: warp-per-roi argmax (coalesced) + decode + clip + compact ----
    for (int i = wid; i < BN; i += 32) {
        const size_t gi = (size_t)b * BN + i;
        const float* pr = probs + gi * CC;

        // lanes cover classes lane, lane+32, lane+64 (coalesced)
        float v0 = pr[lane];
        float v1 = pr[lane + 32];
        float v2 = (lane + 64 < CC) ? pr[lane + 64] : -1.0f;

        float bv = v0; int bc = lane;
        if (v1 > bv) { bv = v1; bc = lane + 32; }
        if (v2 > bv) { bv = v2; bc = lane + 64; }
        #pragma unroll
        for (int off = 16; off > 0; off >>= 1) {
            const float ov = __shfl_xor_sync(0xffffffffu, bv, off);
            const int   oc = __shfl_xor_sync(0xffffffffu, bc, off);
            if (ov > bv || (ov == bv && oc < bc)) { bv = ov; bc = oc; }
        }

        if (lane == 0 && bc > 0 && bv >= MIN_CONF) {
            const float* dl = deltas + (gi * CC + bc) * 4;
            const float dy = dl[0] * 0.1f;
            const float dx = dl[1] * 0.1f;
            const float dh = dl[2] * 0.2f;
            const float dw = dl[3] * 0.2f;

            const float* rr = rois + gi * 4;
            float y1 = rr[0], x1 = rr[1], y2 = rr[2], x2 = rr[3];
            const float h0 = y2 - y1, w0 = x2 - x1;
            const float cy = y1 + 0.5f * h0 + dy * h0;
            const float cx = x1 + 0.5f * w0 + dx * w0;
            const float hh = h0 * expf(dh);
            const float ww = w0 * expf(dw);
            y1 = cy - 0.5f * hh;
            x1 = cx - 0.5f * ww;
            y2 = y1 + hh;
            x2 = x1 + ww;
            y1 = fminf(fmaxf(y1, wy1), wy2);
            x1 = fminf(fmaxf(x1, wx1), wx2);
            y2 = fminf(fmaxf(y2, wy1), wy2);
            x2 = fminf(fmaxf(x2, wx1), wx2);

            const int slot = atomicAdd(&s_nv, 1);
            c_kv[slot]    = ((unsigned long long)float_orderable(-bv) << 32)
                            | (unsigned int)i;
            c_y1[slot] = y1; c_x1[slot] = x1; c_y2[slot] = y2; c_x2[slot] = x2;
            c_score[slot] = bv;
            c_cls[slot]   = bc;
        }
    }
    __syncthreads();
    const int V = s_nv;

    // ---- Phase 2: within-class rank by counting (replaces global sort) ----
    for (int t = tid; t < V; t += NTHR) {
        const unsigned long long kv = c_kv[t];
        const int c = c_cls[t];
        int r = 0;
        for (int q = 0; q < V; q++)
            r += (c_cls[q] == c) && (c_kv[q] < kv);
        c_wr[t] = r;
        atomicAdd(&s_ccount[c], 1);
    }
    __syncthreads();

    // ---- Phase 3: class prefix offsets + scatter into per-class lists ----
    if (tid == 0) {
        int acc = 0;
        for (int c = 0; c < CC; c++) { s_cstart[c] = acc; acc += s_ccount[c]; }
    }
    __syncthreads();
    for (int t = tid; t < V; t += NTHR)
        s_clist[s_cstart[c_cls[t]] + c_wr[t]] = t;
    __syncthreads();

    // ---- Phase 4: per-class greedy NMS, one warp per class ----
    for (int c = wid; c < CC; c += 32) {
        const int n = s_ccount[c];
        if (n == 0) continue;
        const int base = s_cstart[c];
        int kc = 0;
        for (int t = 0; t < n; t++) {
            const int s = s_clist[base + t];
            const float cy1 = c_y1[s], cx1 = c_x1[s];
            const float cy2 = c_y2[s], cx2 = c_x2[s];
            const float ca  = (cy2 - cy1) * (cx2 - cx1);

            bool sup = false;
            for (int q = lane; q < t; q += 32) {
                const int s2 = s_clist[base + q];
                if (s_kept[s2]) {
                    const float yy1 = fmaxf(cy1, c_y1[s2]);
                    const float xx1 = fmaxf(cx1, c_x1[s2]);
                    const float yy2 = fminf(cy2, c_y2[s2]);
                    const float xx2 = fminf(cx2, c_x2[s2]);
                    const float inter = fmaxf(yy2 - yy1, 0.0f) * fmaxf(xx2 - xx1, 0.0f);
                    const float a2 = (c_y2[s2] - c_y1[s2]) * (c_x2[s2] - c_x1[s2]);
                    const float uni = ca + a2 - inter;
                    if (inter / fmaxf(uni, 1e-8f) > NMS_THR) sup = true;
                }
            }
            if (!__any_sync(0xffffffffu, sup)) {
                if (lane == 0) s_kept[s] = 1;
                kc++;
                if (kc == KK) break;      // quota full: no later same-class keeps
            }
            __syncwarp();
        }
    }
    __syncthreads();

    // ---- Phase 5: zero-fill all K output rows ----
    for (int k = tid; k < KK; k += NTHR) {
        const size_t bk = (size_t)b * KK + k;
        float* o = det_out + bk * 6;
        o[0] = 0.0f; o[1] = 0.0f; o[2] = 0.0f;
        o[3] = 0.0f; o[4] = 0.0f; o[5] = 0.0f;
        feat_out[bk * FF] = __int_as_float(-1);
    }
    __syncthreads();

    // ---- Phase 6: global kept-rank by counting; write kept rows ----
    for (int t = tid; t < V; t += NTHR) {
        if (!s_kept[t]) continue;
        const unsigned long long kv = c_kv[t];
        int r = 0;
        for (int q = 0; q < V; q++)
            r += s_kept[q] && (c_kv[q] < kv);
        if (r < KK) {
            const size_t bk = (size_t)b * KK + r;
            float* o = det_out + bk * 6;
            o[0] = c_y1[t];
            o[1] = c_x1[t];
            o[2] = c_y2[t];
            o[3] = c_x2[t];
            o[4] = (float)c_cls[t];
            o[5] = c_score[t];
            feat_out[bk * FF] = __int_as_float((int)(kv & 0xFFFFFFFFu));
        }
    }
}

// =====================================================================
// Kernel B: feature gather. Reads the roi index from dst[0] (written by
// Kernel A), broadcasts it, then copies/zero-fills the full row.
// =====================================================================
__global__ __launch_bounds__(256)
void feat_gather_kernel(const float* __restrict__ obj_feat,
                        float* __restrict__ feat_out)
{
    const int bk = blockIdx.x;            // b*KK + k
    const int b  = bk / KK;
    const int t  = threadIdx.x;           // 256 threads x float4 = 1024 floats

    __shared__ int sj;
    float* dst = feat_out + (size_t)bk * FF;
    if (t == 0) sj = __float_as_int(dst[0]);
    __syncthreads();
    const int j = sj;

    float4* d4 = (float4*)dst;
    if (j >= 0) {
        const float4* s4 = (const float4*)(obj_feat + ((size_t)b * BN + j) * FF);
        d4[t] = s4[t];
    } else {
        d4[t] = make_float4(0.0f, 0.0f, 0.0f, 0.0f);
    }
}

extern "C" void kernel_launch(void* const* d_in, const int* in_sizes, int n_in,
                              void* d_out, int out_size)
{
    const float* rois     = (const float*)d_in[0];
    const float* fpnclass = (const float*)d_in[1];
    const float* fpnbbox  = (const float*)d_in[2];
    const float* objfeat  = (const float*)d_in[3];
    const float* meta     = (const float*)d_in[4];

    const int B = in_sizes[0] / (BN * 4);

    float* det_out  = (float*)d_out;                         // (B, K, 6)
    float* feat_out = (float*)d_out + (size_t)B * KK * 6;    // (B, K, 1, 1, F)

    detect_kernel<<<B, NTHR>>>(rois, fpnclass, fpnbbox, meta, det_out, feat_out);
    feat_gather_kernel<<<B * KK, 256>>>(objfeat, feat_out);
}

// round 8
// speedup vs baseline: 1.9637x; 1.1278x over previous
#include <cuda_runtime.h>
#include <math.h>

// Problem constants (fixed by the dataset's setup_inputs)
#define BN   1000      // rois per image
#define NPAD 1024      // max candidates (compacted)
#define CC   81        // classes
#define KK   100       // max detections
#define FF   1024      // feature dim
#define META_STRIDE (12 + CC)

#define MIN_CONF 0.7f
#define NMS_THR  0.3f

#define NTHR   1024    // threads per detect CTA
#define CHUNK  128     // rois per TMA chunk
#define NCHUNK ((BN + CHUNK - 1) / CHUNK)     // 8 (7 full + 104)
#define CHUNK_FLOATS (CHUNK * CC)             // 10368
#define CHUNK_BYTES  (CHUNK_FLOATS * 4)       // 41472 (16B-aligned)

// ---- dynamic shared memory layout (byte offsets) ----
#define OFF_BUF0   0
#define OFF_BUF1   (CHUNK_BYTES)
#define OFF_KV     (2 * CHUNK_BYTES)              // u64 x NPAD
#define OFF_BOX    (OFF_KV    + NPAD * 8)         // float4 x NPAD
#define OFF_SCORE  (OFF_BOX   + NPAD * 16)        // float x NPAD
#define OFF_CLS    (OFF_SCORE + NPAD * 4)         // int x NPAD
#define OFF_WR     (OFF_CLS   + NPAD * 4)         // int x NPAD
#define OFF_LIST   (OFF_WR    + NPAD * 4)         // int x NPAD
#define OFF_KEPT   (OFF_LIST  + NPAD * 4)         // u8 x NPAD
#define OFF_CCNT   (OFF_KEPT  + NPAD)             // int x CC
#define OFF_CSTART (OFF_CCNT  + CC * 4)           // int x CC
#define OFF_END    (OFF_CSTART + CC * 4)
#define SMEM_SIZE  ((OFF_END + 127) & ~127)       // ~125.7 KB

// order-preserving float -> uint32 (ascending)
__device__ __forceinline__ unsigned int float_orderable(float f) {
    unsigned int u = __float_as_uint(f);
    return u ^ ((u >> 31) ? 0xFFFFFFFFu : 0x80000000u);
}

__device__ __forceinline__ unsigned int smem_u32(const void* p) {
    return (unsigned int)__cvta_generic_to_shared(p);
}

__device__ __forceinline__ void mbar_init(unsigned int a, unsigned int cnt) {
    asm volatile("mbarrier.init.shared.b64 [%0], %1;" :: "r"(a), "r"(cnt) : "memory");
}
__device__ __forceinline__ void mbar_expect_tx(unsigned int a, unsigned int tx) {
    asm volatile("mbarrier.arrive.expect_tx.shared.b64 _, [%0], %1;" :: "r"(a), "r"(tx) : "memory");
}
__device__ __forceinline__ void tma_bulk_1d(unsigned int dst, const void* src,
                                            unsigned int bytes, unsigned int mbar) {
    asm volatile(
        "cp.async.bulk.shared::cluster.global.mbarrier::complete_tx::bytes "
        "[%0], [%1], %2, [%3];"
        :: "r"(dst), "l"(src), "r"(bytes), "r"(mbar) : "memory");
}
__device__ __forceinline__ void mbar_wait(unsigned int a, unsigned int phase) {
    unsigned int done;
    do {
        asm volatile(
            "{\n\t.reg .pred p;\n\t"
            "mbarrier.try_wait.parity.acquire.cta.shared::cta.b64 p, [%1], %2, 0x989680;\n\t"
            "selp.b32 %0, 1, 0, p;\n\t}"
            : "=r"(done) : "r"(a), "r"(phase) : "memory");
    } while (!done);
}

// =====================================================================
// Kernel A: per-image refine + compaction + per-class parallel NMS.
// Phase 1: TMA bulk-copies probs in 128-roi chunks into a 2-deep
// shared-memory pipeline; warp-per-roi argmax runs from shared.
// Box decode deferred to the (few) valid candidates. Ordering resolved
// by counting packed-kv comparisons (== stable argsort of reference).
// =====================================================================
__global__ __launch_bounds__(NTHR)
void detect_kernel(const float* __restrict__ rois,
                   const float* __restrict__ probs,
                   const float* __restrict__ deltas,
                   const float* __restrict__ meta,
                   float* __restrict__ det_out,
                   float* __restrict__ feat_out)
{
    extern __shared__ char smem[];
    float*              buf0    = (float*)(smem + OFF_BUF0);
    float*              buf1    = (float*)(smem + OFF_BUF1);
    unsigned long long* c_kv    = (unsigned long long*)(smem + OFF_KV);
    float4*             c_box   = (float4*)(smem + OFF_BOX);
    float*              c_score = (float*)(smem + OFF_SCORE);
    int*                c_cls   = (int*)(smem + OFF_CLS);
    int*                c_wr    = (int*)(smem + OFF_WR);
    int*                c_list  = (int*)(smem + OFF_LIST);
    unsigned char*      s_kept  = (unsigned char*)(smem + OFF_KEPT);
    int*                s_ccnt  = (int*)(smem + OFF_CCNT);
    int*                s_cst   = (int*)(smem + OFF_CSTART);

    __shared__ unsigned long long s_mbar[2];
    __shared__ int s_nv;

    const int b    = blockIdx.x;
    const int tid  = threadIdx.x;
    const int wid  = tid >> 5;
    const int lane = tid & 31;

    float* bufs[2] = {buf0, buf1};
    const unsigned int mb[2] = {smem_u32(&s_mbar[0]), smem_u32(&s_mbar[1])};

    // ---- init ----
    if (tid == 0) {
        mbar_init(mb[0], 1);
        mbar_init(mb[1], 1);
        s_nv = 0;
    }
    for (int c = tid; c < CC; c += NTHR) s_ccnt[c] = 0;
    for (int i = tid; i < NPAD; i += NTHR) s_kept[i] = 0;
    __syncthreads();

    // ---- Phase 1: TMA-pipelined probs stream + warp-per-roi argmax ----
    const float* probs_b = probs + (size_t)b * BN * CC;
    if (tid == 0) {
        // prologue: chunks 0 and 1
        mbar_expect_tx(mb[0], CHUNK_BYTES);
        tma_bulk_1d(smem_u32(buf0), probs_b, CHUNK_BYTES, mb[0]);
        const int c1 = (NCHUNK > 1) ? ((BN - CHUNK < CHUNK) ? BN - CHUNK : CHUNK) : 0;
        if (NCHUNK > 1) {
            mbar_expect_tx(mb[1], c1 * CC * 4);
            tma_bulk_1d(smem_u32(buf1), probs_b + CHUNK * CC, c1 * CC * 4, mb[1]);
        }
    }
    int phase0 = 0, phase1 = 0;

    for (int k = 0; k < NCHUNK; k++) {
        const int bi  = k & 1;
        const int i0  = k * CHUNK;
        const int cnt = (BN - i0 < CHUNK) ? BN - i0 : CHUNK;

        if (bi == 0) { mbar_wait(mb[0], phase0); phase0 ^= 1; }
        else         { mbar_wait(mb[1], phase1); phase1 ^= 1; }

        const float* pb = bufs[bi];
        for (int r = wid; r < cnt; r += 32) {
            const float* pr = pb + r * CC;
            float v0 = pr[lane];
            float v1 = pr[lane + 32];
            float v2 = (lane + 64 < CC) ? pr[lane + 64] : -1.0f;

            float bv = v0; int bc = lane;
            if (v1 > bv) { bv = v1; bc = lane + 32; }
            if (v2 > bv) { bv = v2; bc = lane + 64; }
            #pragma unroll
            for (int off = 16; off > 0; off >>= 1) {
                const float ov = __shfl_xor_sync(0xffffffffu, bv, off);
                const int   oc = __shfl_xor_sync(0xffffffffu, bc, off);
                if (ov > bv || (ov == bv && oc < bc)) { bv = ov; bc = oc; }
            }
            if (lane == 0 && bc > 0 && bv >= MIN_CONF) {
                const int slot = atomicAdd(&s_nv, 1);
                c_kv[slot]    = ((unsigned long long)float_orderable(-bv) << 32)
                                | (unsigned int)(i0 + r);
                c_score[slot] = bv;
                c_cls[slot]   = bc;
            }
        }
        __syncthreads();   // everyone done reading bufs[bi]

        const int kn = k + 2;
        if (kn < NCHUNK && tid == 0) {
            const int i0n  = kn * CHUNK;
            const int cntn = (BN - i0n < CHUNK) ? BN - i0n : CHUNK;
            const unsigned int mba = (bi == 0) ? mb[0] : mb[1];
            mbar_expect_tx(mba, cntn * CC * 4);
            tma_bulk_1d(smem_u32(bufs[bi]), probs_b + (size_t)i0n * CC,
                        cntn * CC * 4, mba);
        }
    }
    __syncthreads();
    const int V = s_nv;

    // window from image_meta (shape from row 0, window per row)
    const float sy = meta[4] - 1.0f;
    const float sx = meta[5] - 1.0f;
    const float wy1 =  meta[(size_t)b * META_STRIDE + 7]          / sy;
    const float wx1 =  meta[(size_t)b * META_STRIDE + 8]          / sx;
    const float wy2 = (meta[(size_t)b * META_STRIDE + 9] - 1.0f)  / sy;
    const float wx2 = (meta[(size_t)b * META_STRIDE + 10] - 1.0f) / sx;

    // ---- Phase 1b: decode + clip, only for the V valid candidates ----
    for (int t = tid; t < V; t += NTHR) {
        const int i  = (int)(c_kv[t] & 0xFFFFFFFFu);
        const int bc = c_cls[t];
        const size_t gi = (size_t)b * BN + i;

        const float4 dl = *(const float4*)(deltas + (gi * CC + bc) * 4);
        const float dy = dl.x * 0.1f;
        const float dx = dl.y * 0.1f;
        const float dh = dl.z * 0.2f;
        const float dw = dl.w * 0.2f;

        const float4 rr = *(const float4*)(rois + gi * 4);
        float y1 = rr.x, x1 = rr.y, y2 = rr.z, x2 = rr.w;
        const float h0 = y2 - y1, w0 = x2 - x1;
        const float cy = y1 + 0.5f * h0 + dy * h0;
        const float cx = x1 + 0.5f * w0 + dx * w0;
        const float hh = h0 * expf(dh);
        const float ww = w0 * expf(dw);
        y1 = cy - 0.5f * hh;
        x1 = cx - 0.5f * ww;
        y2 = y1 + hh;
        x2 = x1 + ww;
        y1 = fminf(fmaxf(y1, wy1), wy2);
        x1 = fminf(fmaxf(x1, wx1), wx2);
        y2 = fminf(fmaxf(y2, wy1), wy2);
        x2 = fminf(fmaxf(x2, wx1), wx2);
        c_box[t] = make_float4(y1, x1, y2, x2);
    }

    // ---- Phase 2: within-class rank by counting ----
    for (int t = tid; t < V; t += NTHR) {
        const unsigned long long kv = c_kv[t];
        const int c = c_cls[t];
        int r = 0;
        for (int q = 0; q < V; q++)
            r += (c_cls[q] == c) && (c_kv[q] < kv);
        c_wr[t] = r;
        atomicAdd(&s_ccnt[c], 1);
    }
    __syncthreads();

    // ---- Phase 3: class prefix + scatter into per-class lists ----
    if (tid == 0) {
        int acc = 0;
        for (int c = 0; c < CC; c++) { s_cst[c] = acc; acc += s_ccnt[c]; }
    }
    __syncthreads();
    for (int t = tid; t < V; t += NTHR)
        c_list[s_cst[c_cls[t]] + c_wr[t]] = t;
    __syncthreads();

    // ---- Phase 4: per-class greedy NMS, one warp per class ----
    for (int c = wid; c < CC; c += 32) {
        const int n = s_ccnt[c];
        if (n == 0) continue;
        const int base = s_cst[c];
        int kc = 0;
        for (int t = 0; t < n; t++) {
            const int s = c_list[base + t];
            const float4 bx = c_box[s];
            const float ca = (bx.z - bx.x) * (bx.w - bx.y);

            bool sup = false;
            for (int q = lane; q < t; q += 32) {
                const int s2 = c_list[base + q];
                if (s_kept[s2]) {
                    const float4 b2 = c_box[s2];
                    const float yy1 = fmaxf(bx.x, b2.x);
                    const float xx1 = fmaxf(bx.y, b2.y);
                    const float yy2 = fminf(bx.z, b2.z);
                    const float xx2 = fminf(bx.w, b2.w);
                    const float inter = fmaxf(yy2 - yy1, 0.0f) * fmaxf(xx2 - xx1, 0.0f);
                    const float a2  = (b2.z - b2.x) * (b2.w - b2.y);
                    const float uni = ca + a2 - inter;
                    if (inter / fmaxf(uni, 1e-8f) > NMS_THR) sup = true;
                }
            }
            if (!__any_sync(0xffffffffu, sup)) {
                if (lane == 0) s_kept[s] = 1;
                kc++;
                if (kc == KK) break;    // class quota full
            }
            __syncwarp();
        }
    }
    __syncthreads();

    // ---- Phase 5: zero-fill all K output rows ----
    for (int k = tid; k < KK; k += NTHR) {
        const size_t bk = (size_t)b * KK + k;
        float* o = det_out + bk * 6;
        o[0] = 0.0f; o[1] = 0.0f; o[2] = 0.0f;
        o[3] = 0.0f; o[4] = 0.0f; o[5] = 0.0f;
        feat_out[bk * FF] = __int_as_float(-1);
    }
    __syncthreads();

    // ---- Phase 6: global kept-rank by counting; write kept rows ----
    for (int t = tid; t < V; t += NTHR) {
        if (!s_kept[t]) continue;
        const unsigned long long kv = c_kv[t];
        int r = 0;
        for (int q = 0; q < V; q++)
            r += s_kept[q] && (c_kv[q] < kv);
        if (r < KK) {
            const size_t bk = (size_t)b * KK + r;
            const float4 bx = c_box[t];
            float* o = det_out + bk * 6;
            o[0] = bx.x;
            o[1] = bx.y;
            o[2] = bx.z;
            o[3] = bx.w;
            o[4] = (float)c_cls[t];
            o[5] = c_score[t];
            feat_out[bk * FF] = __int_as_float((int)(kv & 0xFFFFFFFFu));
        }
    }
}

// =====================================================================
// Kernel B: feature gather. Reads the roi index from dst[0] (written by
// Kernel A), broadcasts it, then copies/zero-fills the full row.
// =====================================================================
__global__ __launch_bounds__(256)
void feat_gather_kernel(const float* __restrict__ obj_feat,
                        float* __restrict__ feat_out)
{
    const int bk = blockIdx.x;            // b*KK + k
    const int b  = bk / KK;
    const int t  = threadIdx.x;           // 256 threads x float4 = 1024 floats

    __shared__ int sj;
    float* dst = feat_out + (size_t)bk * FF;
    if (t == 0) sj = __float_as_int(dst[0]);
    __syncthreads();
    const int j = sj;

    float4* d4 = (float4*)dst;
    if (j >= 0) {
        const float4* s4 = (const float4*)(obj_feat + ((size_t)b * BN + j) * FF);
        d4[t] = s4[t];
    } else {
        d4[t] = make_float4(0.0f, 0.0f, 0.0f, 0.0f);
    }
}

namespace {
struct SmemOptIn {
    SmemOptIn() {
        cudaFuncSetAttribute(detect_kernel,
                             cudaFuncAttributeMaxDynamicSharedMemorySize, SMEM_SIZE);
    }
};
static SmemOptIn g_smem_optin;
}  // namespace

extern "C" void kernel_launch(void* const* d_in, const int* in_sizes, int n_in,
                              void* d_out, int out_size)
{
    const float* rois     = (const float*)d_in[0];
    const float* fpnclass = (const float*)d_in[1];
    const float* fpnbbox  = (const float*)d_in[2];
    const float* objfeat  = (const float*)d_in[3];
    const float* meta     = (const float*)d_in[4];

    const int B = in_sizes[0] / (BN * 4);

    float* det_out  = (float*)d_out;                         // (B, K, 6)
    float* feat_out = (float*)d_out + (size_t)B * KK * 6;    // (B, K, 1, 1, F)

    detect_kernel<<<B, NTHR, SMEM_SIZE>>>(rois, fpnclass, fpnbbox, meta,
                                          det_out, feat_out);
    feat_gather_kernel<<<B * KK, 256>>>(objfeat, feat_out);
}

// round 10
// speedup vs baseline: 3.7388x; 1.9040x over previous
#include <cuda_runtime.h>
#include <math.h>

// Problem constants (fixed by the dataset's setup_inputs)
#define BN   1000      // rois per image
#define NPAD 1024      // slot count per image (>= BN)
#define CC   81        // classes
#define KK   100       // max detections
#define FF   1024      // feature dim
#define META_STRIDE (12 + CC)

#define MIN_CONF 0.7f
#define NMS_THR  0.3f

#define CHUNK  128     // rois per refine CTA
#define NCHUNK ((BN + CHUNK - 1) / CHUNK)     // 8
#define CHUNK_FLOATS (CHUNK * CC)             // 10368
#define KV_INVALID_HI 0xFFFFFFFFu             // valid kv_hi < 0x80000000

// scratch slot: 8 floats per (image, roi):
//   [0]=kv_hi bits, [1]=roi idx bits, [2]=score, [3]=cls bits, [4..7]=box
// located at feat_out + b*KK*FF + 4 + roi*8  (8-byte aligned; consumed by
// nms_kernel before any conflicting write; overwritten by gather at the end)
#define SCRATCH_OFF 4

// order-preserving float -> uint32 (ascending)
__device__ __forceinline__ unsigned int float_orderable(float f) {
    unsigned int u = __float_as_uint(f);
    return u ^ ((u >> 31) ? 0xFFFFFFFFu : 0x80000000u);
}

__device__ __forceinline__ unsigned int smem_u32(const void* p) {
    return (unsigned int)__cvta_generic_to_shared(p);
}
__device__ __forceinline__ void mbar_init(unsigned int a, unsigned int cnt) {
    asm volatile("mbarrier.init.shared.b64 [%0], %1;" :: "r"(a), "r"(cnt) : "memory");
}
__device__ __forceinline__ void mbar_expect_tx(unsigned int a, unsigned int tx) {
    asm volatile("mbarrier.arrive.expect_tx.shared.b64 _, [%0], %1;" :: "r"(a), "r"(tx) : "memory");
}
__device__ __forceinline__ void tma_bulk_1d(unsigned int dst, const void* src,
                                            unsigned int bytes, unsigned int mbar) {
    asm volatile(
        "cp.async.bulk.shared::cluster.global.mbarrier::complete_tx::bytes "
        "[%0], [%1], %2, [%3];"
        :: "r"(dst), "l"(src), "r"(bytes), "r"(mbar) : "memory");
}
__device__ __forceinline__ void mbar_wait(unsigned int a, unsigned int phase) {
    unsigned int done;
    do {
        asm volatile(
            "{\n\t.reg .pred p;\n\t"
            "mbarrier.try_wait.parity.acquire.cta.shared::cta.b64 p, [%1], %2, 0x989680;\n\t"
            "selp.b32 %0, 1, 0, p;\n\t}"
            : "=r"(done) : "r"(a), "r"(phase) : "memory");
    } while (!done);
}

// =====================================================================
// K1: refine. grid = (NCHUNK, B), 128 threads. One TMA chunk of probs
// into shared; thread-per-roi argmax (conflict-free: stride 81 ≡ 17 mod
// 32); decode+clip for valid rois; write 8-float slot into scratch.
// =====================================================================
__global__ __launch_bounds__(CHUNK)
void refine_kernel(const float* __restrict__ rois,
                   const float* __restrict__ probs,
                   const float* __restrict__ deltas,
                   const float* __restrict__ meta,
                   float* __restrict__ feat_out)
{
    __shared__ __align__(16) float buf[CHUNK_FLOATS];
    __shared__ unsigned long long s_mbar;

    const int chunk = blockIdx.x;
    const int b     = blockIdx.y;
    const int tid   = threadIdx.x;
    const int i0    = chunk * CHUNK;
    const int cnt   = (BN - i0 < CHUNK) ? BN - i0 : CHUNK;

    const unsigned int mb = smem_u32(&s_mbar);
    if (tid == 0) mbar_init(mb, 1);
    __syncthreads();
    if (tid == 0) {
        const unsigned int bytes = (unsigned int)cnt * CC * 4;
        mbar_expect_tx(mb, bytes);
        tma_bulk_1d(smem_u32(buf), probs + ((size_t)b * BN + i0) * CC, bytes, mb);
    }
    mbar_wait(mb, 0);

    float* scratch = feat_out + (size_t)b * KK * FF + SCRATCH_OFF;

    if (tid < cnt) {
        const int i = i0 + tid;
        const float* pr = buf + tid * CC;

        int   best = 0;
        float bs   = pr[0];
        #pragma unroll 8
        for (int c = 1; c < CC; c++) {
            const float v = pr[c];
            if (v > bs) { bs = v; best = c; }   // first-max like jnp.argmax
        }

        float2* slot = (float2*)(scratch + (size_t)i * 8);
        if (best > 0 && bs >= MIN_CONF) {
            // window from image_meta
            const float sy = meta[4] - 1.0f;
            const float sx = meta[5] - 1.0f;
            const float wy1 =  meta[(size_t)b * META_STRIDE + 7]          / sy;
            const float wx1 =  meta[(size_t)b * META_STRIDE + 8]          / sx;
            const float wy2 = (meta[(size_t)b * META_STRIDE + 9] - 1.0f)  / sy;
            const float wx2 = (meta[(size_t)b * META_STRIDE + 10] - 1.0f) / sx;

            const size_t gi = (size_t)b * BN + i;
            const float4 dl = *(const float4*)(deltas + (gi * CC + best) * 4);
            const float dy = dl.x * 0.1f;
            const float dx = dl.y * 0.1f;
            const float dh = dl.z * 0.2f;
            const float dw = dl.w * 0.2f;

            const float4 rr = *(const float4*)(rois + gi * 4);
            float y1 = rr.x, x1 = rr.y, y2 = rr.z, x2 = rr.w;
            const float h0 = y2 - y1, w0 = x2 - x1;
            const float cy = y1 + 0.5f * h0 + dy * h0;
            const float cx = x1 + 0.5f * w0 + dx * w0;
            const float hh = h0 * expf(dh);
            const float ww = w0 * expf(dw);
            y1 = cy - 0.5f * hh;
            x1 = cx - 0.5f * ww;
            y2 = y1 + hh;
            x2 = x1 + ww;
            y1 = fminf(fmaxf(y1, wy1), wy2);
            x1 = fminf(fmaxf(x1, wx1), wx2);
            y2 = fminf(fmaxf(y2, wy1), wy2);
            x2 = fminf(fmaxf(x2, wx1), wx2);

            slot[0] = make_float2(__uint_as_float(float_orderable(-bs)),
                                  __uint_as_float((unsigned int)i));
            slot[1] = make_float2(bs, __int_as_float(best));
            slot[2] = make_float2(y1, x1);
            slot[3] = make_float2(y2, x2);
        } else {
            slot[0] = make_float2(__uint_as_float(KV_INVALID_HI), 0.0f);
        }
    }
}

// =====================================================================
// K2: per-image NMS. grid = B, 1024 threads. Loads scratch slots,
// compacts valid candidates, resolves ordering by counting packed-kv
// comparisons (== stable argsort of reference), runs warp-per-class
// greedy NMS, writes det rows + gather index into feat row slot 0.
// =====================================================================
__global__ __launch_bounds__(NPAD)
void nms_kernel(float* __restrict__ det_out,
                float* __restrict__ feat_out)
{
    __shared__ unsigned long long c_kv[NPAD];
    __shared__ float4 c_box[NPAD];
    __shared__ float  c_score[NPAD];
    __shared__ int    c_cls[NPAD];
    __shared__ int    c_wr[NPAD];
    __shared__ int    c_list[NPAD];
    __shared__ unsigned char s_kept[NPAD];
    __shared__ int    s_ccnt[CC], s_cst[CC];
    __shared__ int    s_nv;

    const int b    = blockIdx.x;
    const int tid  = threadIdx.x;
    const int wid  = tid >> 5;
    const int lane = tid & 31;

    if (tid == 0) s_nv = 0;
    for (int c = tid; c < CC; c += NPAD) s_ccnt[c] = 0;
    s_kept[tid] = 0;
    __syncthreads();

    // ---- load scratch slots, compact valid candidates ----
    const float* scratch = feat_out + (size_t)b * KK * FF + SCRATCH_OFF;
    if (tid < BN) {
        const float2* slot = (const float2*)(scratch + (size_t)tid * 8);
        const float2 s0 = slot[0];
        const unsigned int kv_hi = __float_as_uint(s0.x);
        if (kv_hi != KV_INVALID_HI) {
            const float2 s1 = slot[1];
            const float2 s2 = slot[2];
            const float2 s3 = slot[3];
            const int t = atomicAdd(&s_nv, 1);
            c_kv[t]    = ((unsigned long long)kv_hi << 32)
                         | __float_as_uint(s0.y);
            c_score[t] = s1.x;
            c_cls[t]   = __float_as_int(s1.y);
            c_box[t]   = make_float4(s2.x, s2.y, s3.x, s3.y);
        }
    }
    __syncthreads();
    const int V = s_nv;

    // ---- within-class rank by counting ----
    for (int t = tid; t < V; t += NPAD) {
        const unsigned long long kv = c_kv[t];
        const int c = c_cls[t];
        int r = 0;
        for (int q = 0; q < V; q++)
            r += (c_cls[q] == c) && (c_kv[q] < kv);
        c_wr[t] = r;
        atomicAdd(&s_ccnt[c], 1);
    }
    __syncthreads();

    // ---- class prefix + scatter into per-class lists ----
    if (tid == 0) {
        int acc = 0;
        for (int c = 0; c < CC; c++) { s_cst[c] = acc; acc += s_ccnt[c]; }
    }
    __syncthreads();
    for (int t = tid; t < V; t += NPAD)
        c_list[s_cst[c_cls[t]] + c_wr[t]] = t;
    __syncthreads();

    // ---- per-class greedy NMS, one warp per class ----
    for (int c = wid; c < CC; c += 32) {
        const int n = s_ccnt[c];
        if (n == 0) continue;
        const int base = s_cst[c];
        int kc = 0;
        for (int t = 0; t < n; t++) {
            const int s = c_list[base + t];
            const float4 bx = c_box[s];
            const float ca = (bx.z - bx.x) * (bx.w - bx.y);

            bool sup = false;
            for (int q = lane; q < t; q += 32) {
                const int s2 = c_list[base + q];
                if (s_kept[s2]) {
                    const float4 b2 = c_box[s2];
                    const float yy1 = fmaxf(bx.x, b2.x);
                    const float xx1 = fmaxf(bx.y, b2.y);
                    const float yy2 = fminf(bx.z, b2.z);
                    const float xx2 = fminf(bx.w, b2.w);
                    const float inter = fmaxf(yy2 - yy1, 0.0f) * fmaxf(xx2 - xx1, 0.0f);
                    const float a2  = (b2.z - b2.x) * (b2.w - b2.y);
                    const float uni = ca + a2 - inter;
                    if (inter / fmaxf(uni, 1e-8f) > NMS_THR) sup = true;
                }
            }
            if (!__any_sync(0xffffffffu, sup)) {
                if (lane == 0) s_kept[s] = 1;
                kc++;
                if (kc == KK) break;    // class quota full
            }
            __syncwarp();
        }
    }
    __syncthreads();

    // ---- zero-fill all K output rows ----
    for (int k = tid; k < KK; k += NPAD) {
        const size_t bk = (size_t)b * KK + k;
        float* o = det_out + bk * 6;
        o[0] = 0.0f; o[1] = 0.0f; o[2] = 0.0f;
        o[3] = 0.0f; o[4] = 0.0f; o[5] = 0.0f;
        feat_out[bk * FF] = __int_as_float(-1);
    }
    __syncthreads();

    // ---- global kept-rank by counting; write kept rows ----
    for (int t = tid; t < V; t += NPAD) {
        if (!s_kept[t]) continue;
        const unsigned long long kv = c_kv[t];
        int r = 0;
        for (int q = 0; q < V; q++)
            r += s_kept[q] && (c_kv[q] < kv);
        if (r < KK) {
            const size_t bk = (size_t)b * KK + r;
            const float4 bx = c_box[t];
            float* o = det_out + bk * 6;
            o[0] = bx.x;
            o[1] = bx.y;
            o[2] = bx.z;
            o[3] = bx.w;
            o[4] = (float)c_cls[t];
            o[5] = c_score[t];
            feat_out[bk * FF] = __int_as_float((int)(kv & 0xFFFFFFFFu));
        }
    }
}

// =====================================================================
// K3: feature gather. Reads the roi index from dst[0] (written by K2),
// broadcasts it, then copies/zero-fills the full row.
// =====================================================================
__global__ __launch_bounds__(256)
void feat_gather_kernel(const float* __restrict__ obj_feat,
                        float* __restrict__ feat_out)
{
    const int bk = blockIdx.x;            // b*KK + k
    const int b  = bk / KK;
    const int t  = threadIdx.x;           // 256 threads x float4 = 1024 floats

    __shared__ int sj;
    float* dst = feat_out + (size_t)bk * FF;
    if (t == 0) sj = __float_as_int(dst[0]);
    __syncthreads();
    const int j = sj;

    float4* d4 = (float4*)dst;
    if (j >= 0) {
        const float4* s4 = (const float4*)(obj_feat + ((size_t)b * BN + j) * FF);
        d4[t] = s4[t];
    } else {
        d4[t] = make_float4(0.0f, 0.0f, 0.0f, 0.0f);
    }
}

extern "C" void kernel_launch(void* const* d_in, const int* in_sizes, int n_in,
                              void* d_out, int out_size)
{
    const float* rois     = (const float*)d_in[0];
    const float* fpnclass = (const float*)d_in[1];
    const float* fpnbbox  = (const float*)d_in[2];
    const float* objfeat  = (const float*)d_in[3];
    const float* meta     = (const float*)d_in[4];

    const int B = in_sizes[0] / (BN * 4);

    float* det_out  = (float*)d_out;                         // (B, K, 6)
    float* feat_out = (float*)d_out + (size_t)B * KK * 6;    // (B, K, 1, 1, F)

    dim3 g1(NCHUNK, B);
    refine_kernel<<<g1, CHUNK>>>(rois, fpnclass, fpnbbox, meta, feat_out);
    nms_kernel<<<B, NPAD>>>(det_out, feat_out);
    feat_gather_kernel<<<B * KK, 256>>>(objfeat, feat_out);
}